// round 9
// baseline (speedup 1.0000x reference)
#include <cuda_runtime.h>
#include <cstdint>
#include <math.h>

#define BB   256
#define NNE  65536
#define HB   16384        // 14-bit level-1 bins
#define HBW  (HB/2)       // packed words (2x16-bit counters)
#define TIE_CAP 4096

// ---------------- scratch (static device globals; no allocation) ----------------
__device__ unsigned short g_b16[(size_t)BB * NNE];   // 32 MB: top 16 bits of approx key
__device__ unsigned g_cand[(size_t)BB * NNE];        // 64 MB: (b16<<16 | idx) candidates
__device__ uint2    g_cand2[(size_t)BB * NNE];       // 128 MB: (exact key, idx)
__device__ unsigned g_hist[(size_t)BB * 2 * HBW];    // 16 MB: 2 packed partial hists per row
__device__ unsigned g_p1t16[BB];   // b16 >= this  <=>  bin above p1
__device__ unsigned g_klo[BB], g_khi[BB];  // inclusive b16 candidate range
__device__ int      g_rem[BB];
__device__ int      g_ccnt[BB];

// ---------------- helpers ----------------
__device__ __forceinline__ unsigned float_key(float w) {
    unsigned x = __float_as_uint(w);
    return x ^ ((unsigned)((int)x >> 31) | 0x80000000u);   // order-preserving
}
__device__ __forceinline__ float key_to_float(unsigned key) {
    unsigned x = (key & 0x80000000u) ? (key ^ 0x80000000u) : ~key;
    return __uint_as_float(x);
}

// exact key: must match the reference's float32 op-order bit-for-bit (libdevice logf)
__device__ __forceinline__ unsigned weight_key_exact(float u, float d) {
    float l1 = logf(u + 1e-7f);
    float inner = -l1 + 1e-7f;
    float G = -logf(inner);
    float w = G + logf(d);
    return float_key(w);
}

// approx key: MUFU-based, |w_a - w_e| <= ~6e-5 with the u>0.99 guard
__device__ __forceinline__ unsigned weight_key_approx(float u, float d) {
    float x = u + 1e-7f;
    float l1 = (u > 0.99f) ? logf(x) : __logf(x);  // exact when 1/inner amplifies abs err
    float inner = -l1 + 1e-7f;
    float G = -__logf(inner);
    float w = G + __logf(d);
    return float_key(w);
}

// Block-wide "find bin containing the rem-th largest" over a shared histogram.
template <int BINS, int THREADS>
__device__ __forceinline__ void select_bin(const unsigned* h, unsigned* ss, int rem,
                                           int* out_bin, int* out_rem, unsigned* out_cnt) {
    constexpr int PER = BINS / THREADS;
    int tid = threadIdx.x;
    unsigned s = 0;
#pragma unroll
    for (int j = 0; j < PER; j++) s += h[tid * PER + j];
    ss[tid] = s;
    __syncthreads();
    for (int off = 1; off < THREADS; off <<= 1) {
        unsigned add = (tid + off < THREADS) ? ss[tid + off] : 0u;
        __syncthreads();
        ss[tid] += add;
        __syncthreads();
    }
    unsigned cumGE = ss[tid];
    unsigned cumGT = (tid < THREADS - 1) ? ss[tid + 1] : 0u;
    if (cumGE >= (unsigned)rem && cumGT < (unsigned)rem) {
        unsigned cum = cumGT;
#pragma unroll
        for (int b = PER - 1; b >= 0; --b) {
            unsigned c = h[tid * PER + b];
            if (cum + c >= (unsigned)rem) {
                *out_bin = tid * PER + b;
                *out_rem = rem - (int)cum;
                *out_cnt = c;
                break;
            }
            cum += c;
        }
    }
}

// ---------------- K0: per-row scalars + defaults ----------------
__global__ void k_init(const float* __restrict__ t, float* __restrict__ out) {
    int gid = blockIdx.x * blockDim.x + threadIdx.x;
    if (gid < BB) {
        float tv = t[gid];
        float a = 3.14159265358979323846f * tv * 0.5f;
        float r = 1.0f - cosf(a);
        int k = (int)(65536.0f * r);
        float ta = tv * 0.998f + 0.001f;
        float w = 1.5707963267948966f * sinf(3.14159265358979323846f * ta * 0.5f);
        out[(size_t)BB * NNE + gid] = w;
        g_rem[gid]   = k;
        g_p1t16[gid] = 0xFFFFFFFFu;   // sentinel: nothing above
        g_klo[gid]   = 1u;            // empty candidate range
        g_khi[gid]   = 0u;
        g_ccnt[gid]  = 0;
    }
}

// ---------------- K1: approx keys (b16) + packed 14-bit histogram ----------------
// grid (2, BB), 512 threads; each block owns half a row and its own hist slice.
__global__ void __launch_bounds__(512) k_keys(const float* __restrict__ U,
                                              const float* __restrict__ D) {
    __shared__ unsigned h32[HBW];   // 32 KB: 2 x 16-bit counters per word
    int tid = threadIdx.x;
    for (int i = tid; i < HBW; i += 512) h32[i] = 0u;
    __syncthreads();

    int row = blockIdx.y, half = blockIdx.x;
    int vbase = (row * NNE + half * 32768) >> 2;   // float4 units
    const float4* U4 = (const float4*)U;
    const float4* D4 = (const float4*)D;
    uint2* B2 = (uint2*)g_b16;
#pragma unroll 4
    for (int i = 0; i < 16; i++) {
        int vi = vbase + i * 512 + tid;
        float4 u = U4[vi];
        float4 d = D4[vi];
        unsigned k0 = weight_key_approx(u.x, d.x);
        unsigned k1 = weight_key_approx(u.y, d.y);
        unsigned k2 = weight_key_approx(u.z, d.z);
        unsigned k3 = weight_key_approx(u.w, d.w);
        unsigned b0 = k0 >> 18, b1 = k1 >> 18, b2 = k2 >> 18, b3 = k3 >> 18;
        atomicAdd(&h32[b0 >> 1], 1u << ((b0 & 1) * 16));
        atomicAdd(&h32[b1 >> 1], 1u << ((b1 & 1) * 16));
        atomicAdd(&h32[b2 >> 1], 1u << ((b2 & 1) * 16));
        atomicAdd(&h32[b3 >> 1], 1u << ((b3 & 1) * 16));
        uint2 pk;
        pk.x = (k0 >> 16) | ((k1 >> 16) << 16);
        pk.y = (k2 >> 16) | ((k3 >> 16) << 16);
        B2[vi] = pk;
    }
    __syncthreads();
    unsigned* gh = g_hist + ((size_t)row * 2 + half) * HBW;
    for (int i = tid; i < HBW; i += 512) gh[i] = h32[i];
}

// ---------------- K2: level-1 bin selection + band bounds (one block / row) ----------------
__global__ void __launch_bounds__(256) k_sel1() {
    int row = blockIdx.x;
    int kk = g_rem[row];
    if (kk <= 0) return;                           // defaults select nothing
    int tid = threadIdx.x;
    const unsigned* hA = g_hist + (size_t)row * 2 * HBW;
    const unsigned* hB = hA + HBW;
    __shared__ unsigned ss[256];
    unsigned s = 0;
    // thread owns 64 bins = 32 packed words
    for (int j = 0; j < 32; j++) {
        unsigned a = hA[tid * 32 + j], b = hB[tid * 32 + j];
        s += (a & 0xFFFFu) + (a >> 16) + (b & 0xFFFFu) + (b >> 16);
    }
    ss[tid] = s;
    __syncthreads();
    for (int off = 1; off < 256; off <<= 1) {
        unsigned add = (tid + off < 256) ? ss[tid + off] : 0u;
        __syncthreads();
        ss[tid] += add;
        __syncthreads();
    }
    unsigned cumGE = ss[tid];
    unsigned cumGT = (tid < 255) ? ss[tid + 1] : 0u;
    if (cumGE >= (unsigned)kk && cumGT < (unsigned)kk) {
        unsigned cum = cumGT;
        int p1 = -1, rem = 0;
        for (int wj = 31; wj >= 0; wj--) {
            unsigned a = hA[tid * 32 + wj], b = hB[tid * 32 + wj];
            unsigned chi = (a >> 16) + (b >> 16);
            unsigned clo = (a & 0xFFFFu) + (b & 0xFFFFu);
            if (cum + chi >= (unsigned)kk) { p1 = tid * 64 + wj * 2 + 1; rem = kk - (int)cum; break; }
            cum += chi;
            if (cum + clo >= (unsigned)kk) { p1 = tid * 64 + wj * 2;     rem = kk - (int)cum; break; }
            cum += clo;
        }
        g_rem[row]   = rem;
        g_p1t16[row] = ((unsigned)p1 + 1u) << 2;
        // band: [lo_f - E, hi_f + E] in key space, truncated (conservatively) to 16 bits
        const float E = 1e-3f;
        unsigned keylo = (unsigned)p1 << 18;
        unsigned keyhi = (((unsigned)p1 + 1u) << 18) - 1u;   // wraps correctly at top bin
        unsigned kloK = keylo, khiK = keyhi;
        float lo_f = key_to_float(keylo);
        float hi_f = key_to_float(keyhi);
        if (isfinite(lo_f)) { unsigned tt = float_key(lo_f - E); if (tt < kloK) kloK = tt; }
        if (isfinite(hi_f)) { unsigned tt = float_key(hi_f + E); if (tt > khiK) khiK = tt; }
        g_klo[row] = kloK >> 16;
        g_khi[row] = khiK >> 16;
    }
}

// ---------------- K3: mask write + band-candidate compaction ----------------
// grid (16, BB), 256 threads, 4096 elems/block. Staging worst case = 4096.
__global__ void __launch_bounds__(256) k_scan(float* __restrict__ out) {
    __shared__ unsigned st[4096];
    __shared__ int scnt, sbase;
    int tid = threadIdx.x;
    if (tid == 0) scnt = 0;
    int row = blockIdx.y;
    unsigned p1t = g_p1t16[row], klo = g_klo[row], khi = g_khi[row];
    __syncthreads();

    int ebase = blockIdx.x * 4096;
    int qbase = (row * NNE + ebase) >> 3;    // uint4 = 8 shorts
    const uint4* B4 = (const uint4*)g_b16;
    float4* O4 = (float4*)out;
#pragma unroll
    for (int i = 0; i < 2; i++) {
        int qi = qbase + i * 256 + tid;
        uint4 v = B4[qi];
        int e0 = ebase + ((i * 256 + tid) << 3);
        unsigned b[8];
        b[0] = v.x & 0xFFFFu; b[1] = v.x >> 16;
        b[2] = v.y & 0xFFFFu; b[3] = v.y >> 16;
        b[4] = v.z & 0xFFFFu; b[5] = v.z >> 16;
        b[6] = v.w & 0xFFFFu; b[7] = v.w >> 16;
        float4 m0, m1;
        m0.x = (b[0] >= p1t) ? 1.0f : 0.0f;
        m0.y = (b[1] >= p1t) ? 1.0f : 0.0f;
        m0.z = (b[2] >= p1t) ? 1.0f : 0.0f;
        m0.w = (b[3] >= p1t) ? 1.0f : 0.0f;
        m1.x = (b[4] >= p1t) ? 1.0f : 0.0f;
        m1.y = (b[5] >= p1t) ? 1.0f : 0.0f;
        m1.z = (b[6] >= p1t) ? 1.0f : 0.0f;
        m1.w = (b[7] >= p1t) ? 1.0f : 0.0f;
#pragma unroll
        for (int j = 0; j < 8; j++)
            if (b[j] >= klo && b[j] <= khi)
                st[atomicAdd(&scnt, 1)] = (b[j] << 16) | (unsigned)(e0 + j);
        int oi = (row * NNE + e0) >> 2;
        O4[oi] = m0;
        O4[oi + 1] = m1;
    }
    __syncthreads();
    int c = scnt;
    if (c) {
        if (tid == 0) sbase = atomicAdd(&g_ccnt[row], c);
        __syncthreads();
        unsigned* dst = g_cand + (size_t)row * NNE + sbase;
        for (int i = tid; i < c; i += 256) dst[i] = st[i];
    }
}

// ---------------- K4: exact recompute on candidates + 3-level drill + final mask ----------------
__global__ void __launch_bounds__(1024) k_fin(float* __restrict__ out,
                                              const float* __restrict__ U,
                                              const float* __restrict__ D) {
    int row = blockIdx.x;
    int C = g_ccnt[row];
    if (C == 0) return;
    int tid = threadIdx.x;
    __shared__ unsigned h[2048];
    __shared__ unsigned ss[1024];
    __shared__ int r_bin, r_rem;
    __shared__ unsigned r_cnt;
    __shared__ int sAbove, tie_cnt;
    __shared__ unsigned tie_idx[TIE_CAP];

    unsigned p1t = g_p1t16[row];
    const unsigned* cw = g_cand + (size_t)row * NNE;
    uint2* cx = g_cand2 + (size_t)row * NNE;
    const float* Ur = U + (size_t)row * NNE;
    const float* Dr = D + (size_t)row * NNE;
    if (tid == 0) { sAbove = 0; tie_cnt = 0; }
    h[tid] = 0u; h[tid + 1024] = 0u;
    __syncthreads();

    // exact keys + level-1 hist (bits [31:21]) + above-count
    int myA = 0;
    for (int i = tid; i < C; i += 1024) {
        unsigned wd = cw[i];
        unsigned idx = wd & 0xFFFFu;
        if ((wd >> 16) >= p1t) myA++;
        unsigned ke = weight_key_exact(Ur[idx], Dr[idx]);
        cx[i] = make_uint2(ke, idx);
        atomicAdd(&h[ke >> 21], 1u);
    }
    if (myA) atomicAdd(&sAbove, myA);
    __syncthreads();
    int need = g_rem[row] + sAbove;    // k-th overall == need-th within candidates
    if (need > C) need = C;
    if (need < 1) need = 1;
    select_bin<2048, 1024>(h, ss, need, &r_bin, &r_rem, &r_cnt);
    __syncthreads();
    unsigned pA = (unsigned)r_bin;
    int rem = r_rem;
    __syncthreads();

    // level 2: bits [20:10] among top-11 == pA
    h[tid] = 0u; h[tid + 1024] = 0u;
    __syncthreads();
    for (int i = tid; i < C; i += 1024) {
        unsigned ke = cx[i].x;
        if ((ke >> 21) == pA) atomicAdd(&h[(ke >> 10) & 2047u], 1u);
    }
    __syncthreads();
    select_bin<2048, 1024>(h, ss, rem, &r_bin, &r_rem, &r_cnt);
    __syncthreads();
    unsigned pB = (unsigned)r_bin;
    rem = r_rem;
    unsigned pre22 = (pA << 11) | pB;
    __syncthreads();

    // level 3: bits [9:0]
    h[tid] = 0u;
    __syncthreads();
    for (int i = tid; i < C; i += 1024) {
        unsigned ke = cx[i].x;
        if ((ke >> 10) == pre22) atomicAdd(&h[ke & 1023u], 1u);
    }
    __syncthreads();
    select_bin<1024, 1024>(h, ss, rem, &r_bin, &r_rem, &r_cnt);
    __syncthreads();

    unsigned T = (pA << 21) | (pB << 10) | (unsigned)r_bin;
    int needT = r_rem;
    int cntT = (int)r_cnt;
    float* orow = out + (size_t)row * NNE;

    if (needT == cntT) {
        for (int i = tid; i < C; i += 1024) {
            uint2 cd = cx[i];
            orow[cd.y] = (cd.x >= T) ? 1.0f : 0.0f;   // overwrite ALL candidates
        }
    } else {
        for (int i = tid; i < C; i += 1024) {
            uint2 cd = cx[i];
            if (cd.x > T) orow[cd.y] = 1.0f;
            else if (cd.x < T) orow[cd.y] = 0.0f;
            else {
                int p = atomicAdd(&tie_cnt, 1);
                if (p < TIE_CAP) tie_idx[p] = cd.y;
            }
        }
        __syncthreads();
        int tc = tie_cnt < TIE_CAP ? tie_cnt : TIE_CAP;
        // stable tie-break: lowest original index first (argsort stability)
        for (int i = tid; i < tc; i += 1024) {
            unsigned my = tie_idx[i];
            int rank = 0;
            for (int j = 0; j < tc; j++) rank += (tie_idx[j] < my);
            orow[my] = (rank < needT) ? 1.0f : 0.0f;
        }
    }
}

// ---------------- launch ----------------
extern "C" void kernel_launch(void* const* d_in, const int* in_sizes, int n_in,
                              void* d_out, int out_size) {
    // metadata order: batch (unused), t, U, D
    const float* t = (const float*)d_in[1];
    const float* U = (const float*)d_in[2];
    const float* D = (const float*)d_in[3];
    float* out = (float*)d_out;

    k_init<<<1, 256>>>(t, out);
    k_keys<<<dim3(2, BB), 512>>>(U, D);
    k_sel1<<<BB, 256>>>();
    k_scan<<<dim3(16, BB), 256>>>(out);
    k_fin<<<BB, 1024>>>(out, U, D);
}

// round 10
// speedup vs baseline: 1.2740x; 1.2740x over previous
#include <cuda_runtime.h>
#include <cstdint>
#include <math.h>

#define BB   256
#define NNE  65536
#define H1BINS 4096   // 12-bit level-1 on r-keys (1 + 8 exp + 3 mantissa)
#define TIE_CAP 4096

// ---------------- scratch (static device globals; no allocation) ----------------
__device__ unsigned g_keys[(size_t)BB * NNE];    // 64 MB: order-preserving keys of r = D/inner
__device__ uint2    g_cand[(size_t)BB * NNE];    // 128 MB: (rkey, idx) band candidates
__device__ uint2    g_cand2[(size_t)BB * NNE];   // 128 MB: (exact wkey, idx)
__device__ unsigned g_hist1[BB * H1BINS];        // 4 MB : level-1 histograms
__device__ unsigned g_p1k[BB];    // key >= this  <=>  strictly above selected bin
__device__ unsigned g_klo[BB], g_khi[BB];        // inclusive key candidate band
__device__ int      g_rem[BB];
__device__ int      g_ccnt[BB];

// ---------------- helpers ----------------
__device__ __forceinline__ unsigned float_key(float w) {
    unsigned x = __float_as_uint(w);
    return x ^ ((unsigned)((int)x >> 31) | 0x80000000u);   // order-preserving
}
__device__ __forceinline__ float key_to_float(unsigned key) {
    unsigned x = (key & 0x80000000u) ? (key ^ 0x80000000u) : ~key;
    return __uint_as_float(x);
}

// exact key: matches the reference's float32 op-order bit-for-bit (libdevice logf)
__device__ __forceinline__ unsigned weight_key_exact(float u, float d) {
    float l1 = logf(u + 1e-7f);
    float inner = -l1 + 1e-7f;
    float G = -logf(inner);
    float w = G + logf(d);
    return float_key(w);
}

// monotone-equivalent streaming key: r = d / (1e-7 - log(u+1e-7)); ordering of r
// equals ordering of w up to ~3e-5 in w-space (covered by the 1e-3 band).
// __logf abs-err amplification guard: u > 0.9996 -> exact logf (0.04% of lanes).
// IEEE divide (div.rn) keeps denormal r exact (no FTZ).
__device__ __forceinline__ unsigned weight_key_r(float u, float d) {
    float x = u + 1e-7f;
    float l1 = (u > 0.9996f) ? logf(x) : __logf(x);
    float inner = 1e-7f - l1;            // always > 0 (min ~6e-8)
    float r = d / inner;                 // r >= 0, max ~1.7e7
    return float_key(r);
}

// Block-wide "find bin containing the rem-th largest" over a shared histogram.
template <int BINS, int THREADS>
__device__ __forceinline__ void select_bin(const unsigned* h, unsigned* ss, int rem,
                                           int* out_bin, int* out_rem, unsigned* out_cnt) {
    constexpr int PER = BINS / THREADS;
    int tid = threadIdx.x;
    unsigned s = 0;
#pragma unroll
    for (int j = 0; j < PER; j++) s += h[tid * PER + j];
    ss[tid] = s;
    __syncthreads();
    for (int off = 1; off < THREADS; off <<= 1) {
        unsigned add = (tid + off < THREADS) ? ss[tid + off] : 0u;
        __syncthreads();
        ss[tid] += add;
        __syncthreads();
    }
    unsigned cumGE = ss[tid];
    unsigned cumGT = (tid < THREADS - 1) ? ss[tid + 1] : 0u;
    if (cumGE >= (unsigned)rem && cumGT < (unsigned)rem) {
        unsigned cum = cumGT;
#pragma unroll
        for (int b = PER - 1; b >= 0; --b) {
            unsigned c = h[tid * PER + b];
            if (cum + c >= (unsigned)rem) {
                *out_bin = tid * PER + b;
                *out_rem = rem - (int)cum;
                *out_cnt = c;
                break;
            }
            cum += c;
        }
    }
}

// ---------------- K0: per-row scalars + defaults ----------------
__global__ void k_init(const float* __restrict__ t, float* __restrict__ out) {
    int gid = blockIdx.x * blockDim.x + threadIdx.x;
    if (gid < BB) {
        float tv = t[gid];
        float a = 3.14159265358979323846f * tv * 0.5f;
        float r = 1.0f - cosf(a);
        int k = (int)(65536.0f * r);            // trunc like astype(int32)
        float ta = tv * 0.998f + 0.001f;
        float w = 1.5707963267948966f * sinf(3.14159265358979323846f * ta * 0.5f);
        out[(size_t)BB * NNE + gid] = w;
        g_rem[gid]  = k;
        g_p1k[gid]  = 0xFFFFFFFFu;   // sentinel: nothing above (finite keys < this)
        g_klo[gid]  = 1u;            // empty band
        g_khi[gid]  = 0u;
        g_ccnt[gid] = 0;
    }
}

// ---------------- K1: r-keys + 12-bit level-1 histogram (fused) ----------------
// grid (8, BB), 256 threads, 8192 elems/block (proven round-8 shape).
__global__ void __launch_bounds__(256) k_keys(const float* __restrict__ U,
                                              const float* __restrict__ D) {
    __shared__ unsigned h[H1BINS];
    int tid = threadIdx.x;
    for (int i = tid; i < H1BINS; i += 256) h[i] = 0u;
    __syncthreads();

    int row = blockIdx.y;
    int vbase = (row * NNE + blockIdx.x * 8192) >> 2;  // float4 index
    const float4* U4 = (const float4*)U;
    const float4* D4 = (const float4*)D;
    uint4* K4 = (uint4*)g_keys;
#pragma unroll
    for (int i = 0; i < 8; i++) {
        int vi = vbase + i * 256 + tid;
        float4 u = U4[vi];
        float4 d = D4[vi];
        uint4 kk;
        kk.x = weight_key_r(u.x, d.x);
        kk.y = weight_key_r(u.y, d.y);
        kk.z = weight_key_r(u.z, d.z);
        kk.w = weight_key_r(u.w, d.w);
        K4[vi] = kk;
        atomicAdd(&h[kk.x >> 20], 1u);
        atomicAdd(&h[kk.y >> 20], 1u);
        atomicAdd(&h[kk.z >> 20], 1u);
        atomicAdd(&h[kk.w >> 20], 1u);
    }
    __syncthreads();
    unsigned* gh = g_hist1 + row * H1BINS;
    for (int i = tid; i < H1BINS; i += 256) {
        unsigned c = h[i];
        if (c) atomicAdd(&gh[i], c);
    }
}

// ---------------- K2: level-1 bin selection + band bounds (one block / row) ----------------
__global__ void __launch_bounds__(256) k_sel1() {
    int row = blockIdx.x;
    if (g_rem[row] <= 0) return;                 // defaults select nothing
    int tid = threadIdx.x;
    __shared__ unsigned sh[H1BINS];
    __shared__ unsigned ss[256];
    __shared__ int r_bin, r_rem;
    __shared__ unsigned r_cnt;
    for (int i = tid; i < H1BINS; i += 256) sh[i] = g_hist1[row * H1BINS + i];
    int rem = g_rem[row];
    __syncthreads();
    select_bin<H1BINS, 256>(sh, ss, rem, &r_bin, &r_rem, &r_cnt);
    __syncthreads();
    if (tid == 0) {
        unsigned p1 = (unsigned)r_bin;
        g_rem[row] = r_rem;
        unsigned keylo = p1 << 20;
        unsigned keyhi = ((p1 + 1u) << 20) - 1u;      // wraps to 0xFFFFFFFF for p1=4095
        g_p1k[row] = (p1 == 4095u) ? 0xFFFFFFFFu : ((p1 + 1u) << 20);
        // multiplicative band +-0.1% (r >= 0; >=30x margin over all approx errors)
        unsigned kloK = keylo, khiK = keyhi;
        float lo_f = key_to_float(keylo);
        float hi_f = key_to_float(keyhi);
        if (isfinite(lo_f)) { unsigned tt = float_key(lo_f * 0.999f); if (tt < kloK) kloK = tt; }
        if (isfinite(hi_f)) {
            float e = hi_f * 1.001f;
            unsigned tt = float_key(isfinite(e) ? e : hi_f);
            if (tt > khiK) khiK = tt;
        }
        g_klo[row] = kloK;
        g_khi[row] = khiK;
    }
}

// ---------------- K3: mask write + band-candidate compaction (round-8 proven shape) ----------------
__global__ void __launch_bounds__(256) k_scan(float* __restrict__ out) {
    __shared__ uint2 st[4096];
    __shared__ int scnt, sbase;
    int tid = threadIdx.x;
    if (tid == 0) scnt = 0;
    int row = blockIdx.y;
    unsigned p1k = g_p1k[row], klo = g_klo[row], khi = g_khi[row];
    __syncthreads();

    int ebase = blockIdx.x * 4096;
    int vbase = (row * NNE + ebase) >> 2;
    const uint4* K4 = (const uint4*)g_keys;
    float4* O4 = (float4*)out;
#pragma unroll
    for (int i = 0; i < 4; i++) {
        int vi = vbase + i * 256 + tid;
        uint4 kk = K4[vi];
        int eidx = ebase + ((i * 256 + tid) << 2);
        float4 m;
        m.x = (kk.x >= p1k) ? 1.0f : 0.0f;
        m.y = (kk.y >= p1k) ? 1.0f : 0.0f;
        m.z = (kk.z >= p1k) ? 1.0f : 0.0f;
        m.w = (kk.w >= p1k) ? 1.0f : 0.0f;
        if (kk.x >= klo && kk.x <= khi) st[atomicAdd(&scnt, 1)] = make_uint2(kk.x, (unsigned)(eidx + 0));
        if (kk.y >= klo && kk.y <= khi) st[atomicAdd(&scnt, 1)] = make_uint2(kk.y, (unsigned)(eidx + 1));
        if (kk.z >= klo && kk.z <= khi) st[atomicAdd(&scnt, 1)] = make_uint2(kk.z, (unsigned)(eidx + 2));
        if (kk.w >= klo && kk.w <= khi) st[atomicAdd(&scnt, 1)] = make_uint2(kk.w, (unsigned)(eidx + 3));
        O4[vi] = m;
    }
    __syncthreads();
    int c = scnt;
    if (c) {
        if (tid == 0) sbase = atomicAdd(&g_ccnt[row], c);
        __syncthreads();
        uint2* dst = g_cand + (size_t)row * NNE + sbase;
        for (int i = tid; i < c; i += 256) dst[i] = st[i];
    }
}

// ---------------- K4: exact recompute on candidates + 3-level drill + final mask ----------------
__global__ void __launch_bounds__(1024) k_fin(float* __restrict__ out,
                                              const float* __restrict__ U,
                                              const float* __restrict__ D) {
    int row = blockIdx.x;
    int C = g_ccnt[row];
    if (C == 0) return;
    int tid = threadIdx.x;
    __shared__ unsigned h[2048];
    __shared__ unsigned ss[1024];
    __shared__ int r_bin, r_rem;
    __shared__ unsigned r_cnt;
    __shared__ int sAbove, tie_cnt;
    __shared__ unsigned tie_idx[TIE_CAP];

    unsigned p1k = g_p1k[row];
    const uint2* cw = g_cand + (size_t)row * NNE;
    uint2* cx = g_cand2 + (size_t)row * NNE;
    const float* Ur = U + (size_t)row * NNE;
    const float* Dr = D + (size_t)row * NNE;
    if (tid == 0) { sAbove = 0; tie_cnt = 0; }
    h[tid] = 0u; h[tid + 1024] = 0u;
    __syncthreads();

    // exact w-keys + level-1 hist (bits [31:21]) + count of provisional 1s among candidates
    int myA = 0;
    for (int i = tid; i < C; i += 1024) {
        uint2 wd = cw[i];
        unsigned idx = wd.y;
        if (wd.x >= p1k) myA++;
        unsigned ke = weight_key_exact(Ur[idx], Dr[idx]);
        cx[i] = make_uint2(ke, idx);
        atomicAdd(&h[ke >> 21], 1u);
    }
    if (myA) atomicAdd(&sAbove, myA);
    __syncthreads();
    int need = g_rem[row] + sAbove;    // k-th overall == need-th within candidates
    if (need > C) need = C;
    if (need < 1) need = 1;
    select_bin<2048, 1024>(h, ss, need, &r_bin, &r_rem, &r_cnt);
    __syncthreads();
    unsigned pA = (unsigned)r_bin;
    int rem = r_rem;
    __syncthreads();

    // level 2: bits [20:10]
    h[tid] = 0u; h[tid + 1024] = 0u;
    __syncthreads();
    for (int i = tid; i < C; i += 1024) {
        unsigned ke = cx[i].x;
        if ((ke >> 21) == pA) atomicAdd(&h[(ke >> 10) & 2047u], 1u);
    }
    __syncthreads();
    select_bin<2048, 1024>(h, ss, rem, &r_bin, &r_rem, &r_cnt);
    __syncthreads();
    unsigned pB = (unsigned)r_bin;
    rem = r_rem;
    unsigned pre22 = (pA << 11) | pB;
    __syncthreads();

    // level 3: bits [9:0]
    h[tid] = 0u;
    __syncthreads();
    for (int i = tid; i < C; i += 1024) {
        unsigned ke = cx[i].x;
        if ((ke >> 10) == pre22) atomicAdd(&h[ke & 1023u], 1u);
    }
    __syncthreads();
    select_bin<1024, 1024>(h, ss, rem, &r_bin, &r_rem, &r_cnt);
    __syncthreads();

    unsigned T = (pA << 21) | (pB << 10) | (unsigned)r_bin;
    int needT = r_rem;
    int cntT = (int)r_cnt;
    float* orow = out + (size_t)row * NNE;

    if (needT == cntT) {
        for (int i = tid; i < C; i += 1024) {
            uint2 cd = cx[i];
            orow[cd.y] = (cd.x >= T) ? 1.0f : 0.0f;   // overwrite ALL candidates
        }
    } else {
        for (int i = tid; i < C; i += 1024) {
            uint2 cd = cx[i];
            if (cd.x > T) orow[cd.y] = 1.0f;
            else if (cd.x < T) orow[cd.y] = 0.0f;
            else {
                int p = atomicAdd(&tie_cnt, 1);
                if (p < TIE_CAP) tie_idx[p] = cd.y;
            }
        }
        __syncthreads();
        int tc = tie_cnt < TIE_CAP ? tie_cnt : TIE_CAP;
        // stable tie-break: lowest original index first (argsort stability)
        for (int i = tid; i < tc; i += 1024) {
            unsigned my = tie_idx[i];
            int rank = 0;
            for (int j = 0; j < tc; j++) rank += (tie_idx[j] < my);
            orow[my] = (rank < needT) ? 1.0f : 0.0f;
        }
    }
}

// ---------------- launch ----------------
extern "C" void kernel_launch(void* const* d_in, const int* in_sizes, int n_in,
                              void* d_out, int out_size) {
    // metadata order: batch (unused), t, U, D
    const float* t = (const float*)d_in[1];
    const float* U = (const float*)d_in[2];
    const float* D = (const float*)d_in[3];
    float* out = (float*)d_out;

    void* hist_ptr = nullptr;
    cudaGetSymbolAddress(&hist_ptr, g_hist1);
    cudaMemsetAsync(hist_ptr, 0, (size_t)BB * H1BINS * sizeof(unsigned));

    k_init<<<1, 256>>>(t, out);
    k_keys<<<dim3(8, BB), 256>>>(U, D);
    k_sel1<<<BB, 256>>>();
    k_scan<<<dim3(16, BB), 256>>>(out);
    k_fin<<<BB, 1024>>>(out, U, D);
}

// round 11
// speedup vs baseline: 1.3393x; 1.0513x over previous
#include <cuda_runtime.h>
#include <cstdint>
#include <math.h>

#define BB   256
#define NNE  65536
#define H1BINS 4096   // 12-bit level-1 on r-keys
#define TIE_CAP 4096

// ---------------- scratch (static device globals; no allocation) ----------------
__device__ unsigned short g_b16[(size_t)BB * NNE];   // 32 MB: top 16 bits of r-key
__device__ unsigned g_cand[(size_t)BB * NNE];        // 64 MB: (b16<<16)|idx band candidates
__device__ uint2    g_cand2[(size_t)BB * NNE];       // 128 MB: (exact wkey, idx)
__device__ unsigned g_hist1[BB * H1BINS];            // 4 MB : level-1 histograms
__device__ unsigned g_p1k[BB];    // b16 >= this  <=>  strictly above selected bin (<= 0x10000)
__device__ unsigned g_klo[BB], g_khi[BB];            // inclusive b16 candidate band
__device__ int      g_rem[BB];
__device__ int      g_ccnt[BB];

// ---------------- helpers ----------------
__device__ __forceinline__ unsigned float_key(float w) {
    unsigned x = __float_as_uint(w);
    return x ^ ((unsigned)((int)x >> 31) | 0x80000000u);   // order-preserving
}
__device__ __forceinline__ float key_to_float(unsigned key) {
    unsigned x = (key & 0x80000000u) ? (key ^ 0x80000000u) : ~key;
    return __uint_as_float(x);
}

// exact key: matches the reference's float32 op-order bit-for-bit (libdevice logf)
__device__ __forceinline__ unsigned weight_key_exact(float u, float d) {
    float l1 = logf(u + 1e-7f);
    float inner = -l1 + 1e-7f;
    float G = -logf(inner);
    float w = G + logf(d);
    return float_key(w);
}

// monotone-equivalent streaming key: r = d / (1e-7 - log(u+1e-7)).
// __logf guard for u>0.9996 (abs-err amplification); __fdividef rel err 2^-21
// and FTZ effects stay within one 2^20 key bin -> covered by the 0.1% band.
__device__ __forceinline__ unsigned weight_key_r(float u, float d) {
    float x = u + 1e-7f;
    float l1 = (u > 0.9996f) ? logf(x) : __logf(x);
    float inner = 1e-7f - l1;            // always > 0 (min ~6e-8)
    float r = __fdividef(d, inner);      // r >= 0
    return float_key(r);
}

// Block-wide "find bin containing the rem-th largest" over a shared histogram.
template <int BINS, int THREADS>
__device__ __forceinline__ void select_bin(const unsigned* h, unsigned* ss, int rem,
                                           int* out_bin, int* out_rem, unsigned* out_cnt) {
    constexpr int PER = BINS / THREADS;
    int tid = threadIdx.x;
    unsigned s = 0;
#pragma unroll
    for (int j = 0; j < PER; j++) s += h[tid * PER + j];
    ss[tid] = s;
    __syncthreads();
    for (int off = 1; off < THREADS; off <<= 1) {
        unsigned add = (tid + off < THREADS) ? ss[tid + off] : 0u;
        __syncthreads();
        ss[tid] += add;
        __syncthreads();
    }
    unsigned cumGE = ss[tid];
    unsigned cumGT = (tid < THREADS - 1) ? ss[tid + 1] : 0u;
    if (cumGE >= (unsigned)rem && cumGT < (unsigned)rem) {
        unsigned cum = cumGT;
#pragma unroll
        for (int b = PER - 1; b >= 0; --b) {
            unsigned c = h[tid * PER + b];
            if (cum + c >= (unsigned)rem) {
                *out_bin = tid * PER + b;
                *out_rem = rem - (int)cum;
                *out_cnt = c;
                break;
            }
            cum += c;
        }
    }
}

// ---------------- K0: zero hist + per-row scalars ----------------
__global__ void k_init(const float* __restrict__ t, float* __restrict__ out) {
    int gid = blockIdx.x * blockDim.x + threadIdx.x;
    int stride = gridDim.x * blockDim.x;
    for (int i = gid; i < BB * H1BINS; i += stride) g_hist1[i] = 0u;
    if (gid < BB) {
        float tv = t[gid];
        float a = 3.14159265358979323846f * tv * 0.5f;
        float r = 1.0f - cosf(a);
        int k = (int)(65536.0f * r);            // trunc like astype(int32)
        float ta = tv * 0.998f + 0.001f;
        float w = 1.5707963267948966f * sinf(3.14159265358979323846f * ta * 0.5f);
        out[(size_t)BB * NNE + gid] = w;
        g_rem[gid]  = k;
        g_p1k[gid]  = 0x10000u;      // nothing above (b16 <= 0xFFFF) -> all-zero mask
        g_klo[gid]  = 1u;            // empty band
        g_khi[gid]  = 0u;
        g_ccnt[gid] = 0;
    }
}

// ---------------- K1: b16 r-keys + 12-bit level-1 histogram (fused) ----------------
// grid (8, BB), 256 threads, 8192 elems/block.
__global__ void __launch_bounds__(256) k_keys(const float* __restrict__ U,
                                              const float* __restrict__ D) {
    __shared__ unsigned h[H1BINS];
    int tid = threadIdx.x;
    for (int i = tid; i < H1BINS; i += 256) h[i] = 0u;
    __syncthreads();

    int row = blockIdx.y;
    int vbase = (row * NNE + blockIdx.x * 8192) >> 2;  // float4 / uint2 index
    const float4* U4 = (const float4*)U;
    const float4* D4 = (const float4*)D;
    uint2* B2 = (uint2*)g_b16;                          // uint2 = 4 b16 = 4 elements
#pragma unroll
    for (int i = 0; i < 8; i++) {
        int vi = vbase + i * 256 + tid;
        float4 u = U4[vi];
        float4 d = D4[vi];
        unsigned k0 = weight_key_r(u.x, d.x);
        unsigned k1 = weight_key_r(u.y, d.y);
        unsigned k2 = weight_key_r(u.z, d.z);
        unsigned k3 = weight_key_r(u.w, d.w);
        uint2 pk;
        pk.x = (k0 >> 16) | ((k1 >> 16) << 16);
        pk.y = (k2 >> 16) | ((k3 >> 16) << 16);
        B2[vi] = pk;
        atomicAdd(&h[k0 >> 20], 1u);
        atomicAdd(&h[k1 >> 20], 1u);
        atomicAdd(&h[k2 >> 20], 1u);
        atomicAdd(&h[k3 >> 20], 1u);
    }
    __syncthreads();
    unsigned* gh = g_hist1 + row * H1BINS;
    for (int i = tid; i < H1BINS; i += 256) {
        unsigned c = h[i];
        if (c) atomicAdd(&gh[i], c);
    }
}

// ---------------- K2: level-1 bin selection + band bounds (one block / row) ----------------
__global__ void __launch_bounds__(256) k_sel1() {
    int row = blockIdx.x;
    if (g_rem[row] <= 0) return;                 // defaults select nothing
    int tid = threadIdx.x;
    __shared__ unsigned sh[H1BINS];
    __shared__ unsigned ss[256];
    __shared__ int r_bin, r_rem;
    __shared__ unsigned r_cnt;
    for (int i = tid; i < H1BINS; i += 256) sh[i] = g_hist1[row * H1BINS + i];
    int rem = g_rem[row];
    __syncthreads();
    select_bin<H1BINS, 256>(sh, ss, rem, &r_bin, &r_rem, &r_cnt);
    __syncthreads();
    if (tid == 0) {
        unsigned p1 = (unsigned)r_bin;
        g_rem[row] = r_rem;
        g_p1k[row] = (p1 + 1u) << 4;                  // b16-space threshold (bin-aligned)
        // band = selected bin extended +-0.1% multiplicative (r >= 0), then >>16
        unsigned keylo = p1 << 20;
        unsigned keyhi = ((p1 + 1u) << 20) - 1u;
        unsigned kloK = keylo, khiK = keyhi;
        float lo_f = key_to_float(keylo);
        float hi_f = key_to_float(keyhi);
        if (isfinite(lo_f)) { unsigned tt = float_key(lo_f * 0.999f); if (tt < kloK) kloK = tt; }
        if (isfinite(hi_f)) {
            float e = hi_f * 1.001f;
            unsigned tt = float_key(isfinite(e) ? e : hi_f);
            if (tt > khiK) khiK = tt;
        }
        g_klo[row] = kloK >> 16;
        g_khi[row] = khiK >> 16;
    }
}

// ---------------- K3: mask write + band-candidate compaction ----------------
// grid (16, BB), 256 threads, 4096 elems/block; 8 elems/thread/iter via uint4.
__global__ void __launch_bounds__(256) k_scan(float* __restrict__ out) {
    __shared__ unsigned st[4096];
    __shared__ int scnt, sbase;
    int tid = threadIdx.x;
    if (tid == 0) scnt = 0;
    int row = blockIdx.y;
    unsigned thr = g_p1k[row], klo = g_klo[row], khi = g_khi[row];
    __syncthreads();

    int ebase = blockIdx.x * 4096;
    int qbase = (row * NNE + ebase) >> 3;    // uint4 = 8 shorts
    const uint4* B4 = (const uint4*)g_b16;
    float4* O4 = (float4*)out;
#pragma unroll
    for (int i = 0; i < 2; i++) {
        int qi = qbase + i * 256 + tid;
        uint4 v = B4[qi];
        int e0 = ebase + ((i * 256 + tid) << 3);
        unsigned b[8];
        b[0] = v.x & 0xFFFFu; b[1] = v.x >> 16;
        b[2] = v.y & 0xFFFFu; b[3] = v.y >> 16;
        b[4] = v.z & 0xFFFFu; b[5] = v.z >> 16;
        b[6] = v.w & 0xFFFFu; b[7] = v.w >> 16;
        float4 m0, m1;
        m0.x = (b[0] >= thr) ? 1.0f : 0.0f;
        m0.y = (b[1] >= thr) ? 1.0f : 0.0f;
        m0.z = (b[2] >= thr) ? 1.0f : 0.0f;
        m0.w = (b[3] >= thr) ? 1.0f : 0.0f;
        m1.x = (b[4] >= thr) ? 1.0f : 0.0f;
        m1.y = (b[5] >= thr) ? 1.0f : 0.0f;
        m1.z = (b[6] >= thr) ? 1.0f : 0.0f;
        m1.w = (b[7] >= thr) ? 1.0f : 0.0f;
#pragma unroll
        for (int j = 0; j < 8; j++)
            if (b[j] >= klo && b[j] <= khi)
                st[atomicAdd(&scnt, 1)] = (b[j] << 16) | (unsigned)(e0 + j);
        int oi = (row * NNE + e0) >> 2;
        O4[oi]     = m0;
        O4[oi + 1] = m1;
    }
    __syncthreads();
    int c = scnt;
    if (c) {
        if (tid == 0) sbase = atomicAdd(&g_ccnt[row], c);
        __syncthreads();
        unsigned* dst = g_cand + (size_t)row * NNE + sbase;
        for (int i = tid; i < c; i += 256) dst[i] = st[i];
    }
}

// ---------------- K4: exact recompute on candidates + 3-level drill + final mask ----------------
__global__ void __launch_bounds__(1024) k_fin(float* __restrict__ out,
                                              const float* __restrict__ U,
                                              const float* __restrict__ D) {
    int row = blockIdx.x;
    int C = g_ccnt[row];
    if (C == 0) return;
    int tid = threadIdx.x;
    __shared__ unsigned h[2048];
    __shared__ unsigned ss[1024];
    __shared__ int r_bin, r_rem;
    __shared__ unsigned r_cnt;
    __shared__ int sAbove, tie_cnt;
    __shared__ unsigned tie_idx[TIE_CAP];

    unsigned thr = g_p1k[row];
    const unsigned* cw = g_cand + (size_t)row * NNE;
    uint2* cx = g_cand2 + (size_t)row * NNE;
    const float* Ur = U + (size_t)row * NNE;
    const float* Dr = D + (size_t)row * NNE;
    if (tid == 0) { sAbove = 0; tie_cnt = 0; }
    h[tid] = 0u; h[tid + 1024] = 0u;
    __syncthreads();

    // exact w-keys + level-1 hist (bits [31:21]) + count of provisional 1s among candidates
    int myA = 0;
    for (int i = tid; i < C; i += 1024) {
        unsigned wd = cw[i];
        unsigned idx = wd & 0xFFFFu;
        if ((wd >> 16) >= thr) myA++;
        unsigned ke = weight_key_exact(Ur[idx], Dr[idx]);
        cx[i] = make_uint2(ke, idx);
        atomicAdd(&h[ke >> 21], 1u);
    }
    if (myA) atomicAdd(&sAbove, myA);
    __syncthreads();
    int need = g_rem[row] + sAbove;    // k-th overall == need-th within candidates
    if (need > C) need = C;
    if (need < 1) need = 1;
    select_bin<2048, 1024>(h, ss, need, &r_bin, &r_rem, &r_cnt);
    __syncthreads();
    unsigned pA = (unsigned)r_bin;
    int rem = r_rem;
    __syncthreads();

    // level 2: bits [20:10]
    h[tid] = 0u; h[tid + 1024] = 0u;
    __syncthreads();
    for (int i = tid; i < C; i += 1024) {
        unsigned ke = cx[i].x;
        if ((ke >> 21) == pA) atomicAdd(&h[(ke >> 10) & 2047u], 1u);
    }
    __syncthreads();
    select_bin<2048, 1024>(h, ss, rem, &r_bin, &r_rem, &r_cnt);
    __syncthreads();
    unsigned pB = (unsigned)r_bin;
    rem = r_rem;
    unsigned pre22 = (pA << 11) | pB;
    __syncthreads();

    // level 3: bits [9:0]
    h[tid] = 0u;
    __syncthreads();
    for (int i = tid; i < C; i += 1024) {
        unsigned ke = cx[i].x;
        if ((ke >> 10) == pre22) atomicAdd(&h[ke & 1023u], 1u);
    }
    __syncthreads();
    select_bin<1024, 1024>(h, ss, rem, &r_bin, &r_rem, &r_cnt);
    __syncthreads();

    unsigned T = (pA << 21) | (pB << 10) | (unsigned)r_bin;
    int needT = r_rem;
    int cntT = (int)r_cnt;
    float* orow = out + (size_t)row * NNE;

    if (needT == cntT) {
        for (int i = tid; i < C; i += 1024) {
            uint2 cd = cx[i];
            orow[cd.y] = (cd.x >= T) ? 1.0f : 0.0f;   // overwrite ALL candidates
        }
    } else {
        for (int i = tid; i < C; i += 1024) {
            uint2 cd = cx[i];
            if (cd.x > T) orow[cd.y] = 1.0f;
            else if (cd.x < T) orow[cd.y] = 0.0f;
            else {
                int p = atomicAdd(&tie_cnt, 1);
                if (p < TIE_CAP) tie_idx[p] = cd.y;
            }
        }
        __syncthreads();
        int tc = tie_cnt < TIE_CAP ? tie_cnt : TIE_CAP;
        // stable tie-break: lowest original index first (argsort stability)
        for (int i = tid; i < tc; i += 1024) {
            unsigned my = tie_idx[i];
            int rank = 0;
            for (int j = 0; j < tc; j++) rank += (tie_idx[j] < my);
            orow[my] = (rank < needT) ? 1.0f : 0.0f;
        }
    }
}

// ---------------- launch ----------------
extern "C" void kernel_launch(void* const* d_in, const int* in_sizes, int n_in,
                              void* d_out, int out_size) {
    // metadata order: batch (unused), t, U, D
    const float* t = (const float*)d_in[1];
    const float* U = (const float*)d_in[2];
    const float* D = (const float*)d_in[3];
    float* out = (float*)d_out;

    k_init<<<64, 256>>>(t, out);
    k_keys<<<dim3(8, BB), 256>>>(U, D);
    k_sel1<<<BB, 256>>>();
    k_scan<<<dim3(16, BB), 256>>>(out);
    k_fin<<<BB, 1024>>>(out, U, D);
}